// round 2
// baseline (speedup 1.0000x reference)
#include <cuda_runtime.h>
#include <math.h>

#define BB 2
#define CC 64
#define NN 16384
#define DD 3
#define KK 128
#define EE 262144
#define FD 576   // 128 cos + 128 sin + 64 x + 192 gradf + 64 h

// ---------------- scratch (static device globals; no runtime alloc) ----------------
__device__ float d_feat[BB * FD * NN];        // feature matrix (B, 576, N)
__device__ float d_xT[BB * NN * CC];          // x transposed (B, N, C)
__device__ float d_gradf[BB * NN * 192];      // scatter result (B, N, 192)
__device__ float d_xc[BB * CC * KK];
__device__ float d_xs[BB * CC * KK];
__device__ float d_x0[BB * CC];
__device__ float d_Wcat[BB * CC * FD];        // fused left matrix (B, 64, 576)
__device__ float d_bias[BB * CC];             // f_0
__device__ float d_T[BB * CC * NN];           // wx @ x
__device__ float d_wcT[KK * CC * CC];         // weights_c transposed to (k,i,o)
__device__ float d_wsT[KK * CC * CC];
__device__ int   d_cnt[BB * NN];
__device__ int   d_off[BB * (NN + 1)];
__device__ int   d_cur[BB * NN];
__device__ int   d_perm[BB * EE];

// ---------------- zero accumulators ----------------
__global__ void k_zero() {
    int i = blockIdx.x * blockDim.x + threadIdx.x;
    if (i < BB * NN) d_cnt[i] = 0;
    if (i < BB * CC * KK) { d_xc[i] = 0.f; d_xs[i] = 0.f; }
    if (i < BB * CC) d_x0[i] = 0.f;
}

// ---------------- bases: cos/sin(nodes . modes) -> feat rows [0,256) ----------------
__global__ void k_bases(const float* __restrict__ nodes, const float* __restrict__ modes) {
    int n = blockIdx.x * blockDim.x + threadIdx.x;
    int k = blockIdx.y, b = blockIdx.z;
    float p0 = nodes[(b * NN + n) * 3 + 0];
    float p1 = nodes[(b * NN + n) * 3 + 1];
    float p2 = nodes[(b * NN + n) * 3 + 2];
    float t = p0 * modes[k * 3 + 0] + p1 * modes[k * 3 + 1] + p2 * modes[k * 3 + 2];
    float s, c;
    __sincosf(t, &s, &c);
    d_feat[(b * FD + k) * NN + n] = c;
    d_feat[(b * FD + KK + k) * NN + n] = s;
}

// ---------------- copy x -> feat rows [256,320) ----------------
__global__ void k_copyx(const float* __restrict__ x) {
    int i = blockIdx.x * 256 + threadIdx.x;   // over BB*CC*NN, layout matches
    int n = i & (NN - 1);
    int c = (i >> 14) & 63;
    int b = i >> 20;
    d_feat[(b * FD + 256 + c) * NN + n] = x[i];
}

// ---------------- transpose x -> xT (B,N,C) for edge gathers ----------------
__global__ void k_xT(const float* __restrict__ x) {
    __shared__ float tile[32][33];
    int b = blockIdx.z;
    int n0 = blockIdx.x * 32, c0 = blockIdx.y * 32;
    int tx = threadIdx.x, ty = threadIdx.y;   // (32, 8)
    for (int j = 0; j < 32; j += 8)
        tile[ty + j][tx] = x[(b * CC + c0 + ty + j) * NN + n0 + tx];
    __syncthreads();
    for (int j = 0; j < 32; j += 8)
        d_xT[(b * NN + n0 + ty + j) * CC + c0 + tx] = tile[tx][ty + j];
}

// ---------------- GEMM1: x_c[i,k]=sum_n x*nw*cos, x_s=-sum x*nw*sin, x_0=sum x*nw ----
__global__ __launch_bounds__(256) void k_gemm1(const float* __restrict__ x,
                                               const float* __restrict__ nwp) {
    const int b = blockIdx.y;
    const int nbase = blockIdx.x * 128;   // 128 chunks of 128 n
    __shared__ float sx[CC][33];
    __shared__ float sc[KK][33];
    __shared__ float ss[KK][33];
    int t = threadIdx.x;
    int ti = t & 15, tk = t >> 4;
    float aC[4][8] = {}, aS[4][8] = {}, a0[4] = {};
    for (int sub = 0; sub < 4; ++sub) {
        int n0 = nbase + sub * 32;
        #pragma unroll
        for (int j = 0; j < 8; ++j) {
            int e = t + j * 256; int r = e >> 5, col = e & 31;
            sx[r][col] = x[(b * CC + r) * NN + n0 + col] * nwp[b * NN + n0 + col];
        }
        #pragma unroll
        for (int j = 0; j < 16; ++j) {
            int e = t + j * 256; int r = e >> 5, col = e & 31;
            sc[r][col] = d_feat[(b * FD + r) * NN + n0 + col];
            ss[r][col] = d_feat[(b * FD + KK + r) * NN + n0 + col];
        }
        __syncthreads();
        for (int nn = 0; nn < 32; ++nn) {
            float xv[4];
            #pragma unroll
            for (int q = 0; q < 4; ++q) xv[q] = sx[ti + 16 * q][nn];
            if (tk == 0) {
                #pragma unroll
                for (int q = 0; q < 4; ++q) a0[q] += xv[q];
            }
            #pragma unroll
            for (int j = 0; j < 8; ++j) {
                float cv = sc[tk * 8 + j][nn];
                float sv = ss[tk * 8 + j][nn];
                #pragma unroll
                for (int q = 0; q < 4; ++q) {
                    aC[q][j] += xv[q] * cv;
                    aS[q][j] += xv[q] * sv;
                }
            }
        }
        __syncthreads();
    }
    #pragma unroll
    for (int q = 0; q < 4; ++q)
        #pragma unroll
        for (int j = 0; j < 8; ++j) {
            int i = ti + 16 * q, k = tk * 8 + j;
            atomicAdd(&d_xc[(b * CC + i) * KK + k], aC[q][j]);
            atomicAdd(&d_xs[(b * CC + i) * KK + k], -aS[q][j]);   // x_s = -sum
        }
    if (tk == 0)
        #pragma unroll
        for (int q = 0; q < 4; ++q)
            atomicAdd(&d_x0[b * CC + ti + 16 * q], a0[q]);
}

// ---------------- transpose weights_c/s (i,o,k) -> (k,i,o) ----------------
__global__ void k_wT(const float* __restrict__ wc, const float* __restrict__ ws) {
    int i = blockIdx.x * 256 + threadIdx.x;   // over KK*CC*CC
    int o = i & 63; int ii = (i >> 6) & 63; int k = i >> 12;
    d_wcT[i] = wc[(ii * 64 + o) * KK + k];
    d_wsT[i] = ws[(ii * 64 + o) * KK + k];
}

// ---------------- fourier mixing: f_c, f_s -> Wcat cols [0,256) ----------------
__global__ void k_fmix() {
    int k = blockIdx.x, b = blockIdx.y, o = threadIdx.x;
    __shared__ float sxc[64], sxs[64];
    sxc[o] = d_xc[(b * CC + o) * KK + k];
    sxs[o] = d_xs[(b * CC + o) * KK + k];
    __syncthreads();
    float fc = 0.f, fs = 0.f;
    for (int i = 0; i < 64; ++i) {
        float wc = d_wcT[(k * 64 + i) * 64 + o];
        float ws = d_wsT[(k * 64 + i) * 64 + o];
        fc += sxc[i] * wc - sxs[i] * ws;
        fs += sxs[i] * wc + sxc[i] * ws;
    }
    d_Wcat[(b * CC + o) * FD + k] = 2.f * fc;
    d_Wcat[(b * CC + o) * FD + KK + k] = -2.f * fs;
}

// ---------------- Wcat static columns: W, gw, w2 ----------------
__global__ void k_wcat_static(const float* __restrict__ W, const float* __restrict__ gwM,
                              const float* __restrict__ w2) {
    int i = blockIdx.x * 256 + threadIdx.x;   // over BB*CC*320
    if (i >= BB * CC * 320) return;
    int j = i % 320; int o = (i / 320) % CC; int b = i / (320 * CC);
    float v; int col;
    if (j < 64)       { v = W[o * 64 + j];          col = 256 + j; }
    else if (j < 256) { v = gwM[o * 192 + (j - 64)]; col = 320 + (j - 64); }
    else              { v = w2[o * 64 + (j - 256)]; col = 512 + (j - 256); }
    d_Wcat[(b * CC + o) * FD + col] = v;
}

// ---------------- bias f_0 = x_0 @ weights_0 ----------------
__global__ void k_bias(const float* __restrict__ w0) {
    int b = blockIdx.x, o = threadIdx.x;
    __shared__ float s0[64];
    s0[o] = d_x0[b * CC + o];
    __syncthreads();
    float f = 0.f;
    for (int i = 0; i < 64; ++i) f += s0[i] * w0[i * 64 + o];
    d_bias[b * CC + o] = f;
}

// ---------------- edge CSR: count -> scan -> fill ----------------
__global__ void k_count(const int* __restrict__ edges) {
    int i = blockIdx.x * 256 + threadIdx.x;   // b*EE + e
    int tgt = edges[2 * i];
    int b = i / EE;
    atomicAdd(&d_cnt[b * NN + tgt], 1);
}

__global__ void k_scan() {
    int b = blockIdx.x; int t = threadIdx.x;  // 1024 threads
    __shared__ int sm[1024];
    int vals[16]; int run = 0;
    #pragma unroll
    for (int j = 0; j < 16; ++j) {
        int v = d_cnt[b * NN + t * 16 + j];
        vals[j] = run; run += v;
    }
    sm[t] = run; __syncthreads();
    for (int off = 1; off < 1024; off <<= 1) {
        int v = (t >= off) ? sm[t - off] : 0;
        __syncthreads();
        sm[t] += v;
        __syncthreads();
    }
    int prev = (t > 0) ? sm[t - 1] : 0;
    #pragma unroll
    for (int j = 0; j < 16; ++j) {
        int val = prev + vals[j];
        d_off[b * (NN + 1) + t * 16 + j] = val;
        d_cur[b * NN + t * 16 + j] = val;
    }
    if (t == 1023) d_off[b * (NN + 1) + NN] = sm[1023];
}

__global__ void k_fill(const int* __restrict__ edges) {
    int i = blockIdx.x * 256 + threadIdx.x;   // b*EE + e
    int b = i / EE; int e = i - b * EE;
    int tgt = edges[2 * i];
    int slot = atomicAdd(&d_cur[b * NN + tgt], 1);
    d_perm[b * EE + slot] = e;
}

// ---------------- gather: warp per node, register accumulation (no float atomics) ----
__global__ void k_gather(const int* __restrict__ edges, const float* __restrict__ egw) {
    int wid = (blockIdx.x * blockDim.x + threadIdx.x) >> 5;
    int lane = threadIdx.x & 31;
    if (wid >= BB * NN) return;
    int b = wid >> 14, n = wid & (NN - 1);
    const float* xb = &d_xT[b * NN * CC];
    float t0 = xb[n * CC + lane], t1 = xb[n * CC + lane + 32];
    float a0 = 0, a1 = 0, a2 = 0, a3 = 0, a4 = 0, a5 = 0;
    int s = d_off[b * (NN + 1) + n], e_ = d_off[b * (NN + 1) + n + 1];
    for (int p = s; p < e_; ++p) {
        int e = d_perm[b * EE + p];
        int src = edges[(b * EE + e) * 2 + 1];
        float dd0 = xb[src * CC + lane] - t0;
        float dd1 = xb[src * CC + lane + 32] - t1;
        float w0_ = egw[(b * EE + e) * 3 + 0];
        float w1_ = egw[(b * EE + e) * 3 + 1];
        float w2_ = egw[(b * EE + e) * 3 + 2];
        a0 += dd0 * w0_; a1 += dd0 * w1_; a2 += dd0 * w2_;
        a3 += dd1 * w0_; a4 += dd1 * w1_; a5 += dd1 * w2_;
    }
    float* g = &d_gradf[(b * NN + n) * 192];
    g[lane * 3 + 0] = a0; g[lane * 3 + 1] = a1; g[lane * 3 + 2] = a2;
    g[(lane + 32) * 3 + 0] = a3; g[(lane + 32) * 3 + 1] = a4; g[(lane + 32) * 3 + 2] = a5;
}

// ---------------- transpose gradf (N,192) -> feat rows [320,512) ----------------
__global__ void k_gT() {
    __shared__ float tile[32][33];
    int b = blockIdx.z;
    int n0 = blockIdx.x * 32, g0 = blockIdx.y * 32;
    int tx = threadIdx.x, ty = threadIdx.y;   // (32, 8)
    for (int j = 0; j < 32; j += 8)
        tile[ty + j][tx] = d_gradf[(b * NN + n0 + ty + j) * 192 + g0 + tx];
    __syncthreads();
    for (int j = 0; j < 32; j += 8)
        d_feat[(b * FD + 320 + g0 + ty + j) * NN + n0 + tx] = tile[tx][ty + j];
}

// ---------------- generic 64 x KD x N GEMM body ----------------
template <int KD, bool DOGELU>
__device__ __forceinline__ void gemm64_body(const float* __restrict__ A, int aStride,
                                            const float* __restrict__ Bm,
                                            const float* __restrict__ bias,
                                            float* __restrict__ outp) {
    __shared__ __align__(16) float As[16][65];
    __shared__ __align__(16) float Bs[16][132];
    int b = blockIdx.y;
    int n0 = blockIdx.x * 128;
    int t = threadIdx.x;
    int lane = t & 31, wq = t >> 5;
    int to = wq * 8;
    float acc[8][4] = {};
    const float* Ab = A + b * aStride;
    const float* Bb = Bm + b * KD * NN;
    for (int kt = 0; kt < KD / 16; ++kt) {
        #pragma unroll
        for (int j = 0; j < 4; ++j) {
            int e = t + j * 256; int o = e >> 4, kk = e & 15;
            As[kk][o] = Ab[o * KD + kt * 16 + kk];
        }
        #pragma unroll
        for (int j = 0; j < 8; ++j) {
            int e = t + j * 256; int kk = e >> 7, nn = e & 127;
            Bs[kk][nn] = Bb[(kt * 16 + kk) * NN + n0 + nn];
        }
        __syncthreads();
        #pragma unroll
        for (int kk = 0; kk < 16; ++kk) {
            float4 bv = *reinterpret_cast<const float4*>(&Bs[kk][4 * lane]);
            #pragma unroll
            for (int r = 0; r < 8; ++r) {
                float av = As[kk][to + r];
                acc[r][0] += av * bv.x; acc[r][1] += av * bv.y;
                acc[r][2] += av * bv.z; acc[r][3] += av * bv.w;
            }
        }
        __syncthreads();
    }
    #pragma unroll
    for (int r = 0; r < 8; ++r) {
        int o = to + r;
        float bs = DOGELU ? bias[b * CC + o] : 0.f;
        float4 v;
        float* vp = &v.x;
        #pragma unroll
        for (int j = 0; j < 4; ++j) {
            float u = acc[r][j] + bs;
            if (DOGELU) u = 0.5f * u * (1.f + erff(u * 0.70710678118654752f));
            vp[j] = u;
        }
        *reinterpret_cast<float4*>(&outp[(b * CC + o) * NN + n0 + 4 * lane]) = v;
    }
}

__global__ __launch_bounds__(256) void k_gemm_T(const float* __restrict__ wx,
                                                const float* __restrict__ x) {
    gemm64_body<64, false>(wx, 0, x, nullptr, d_T);
}

__global__ __launch_bounds__(256) void k_gemm_final(float* __restrict__ outp) {
    gemm64_body<576, true>(d_Wcat, CC * FD, d_feat, d_bias, outp);
}

// ---------------- h = softsign(geo_wx @ geo) * (wx @ x) -> feat rows [512,576) ------
__global__ void k_h(const float* __restrict__ geo, const float* __restrict__ geo_wx) {
    int i = blockIdx.x * 256 + threadIdx.x;   // BB*CC*NN
    int n = i & (NN - 1); int o = (i >> 14) & 63; int b = i >> 20;
    float g = geo_wx[o * 3 + 0] * geo[(b * 3 + 0) * NN + n]
            + geo_wx[o * 3 + 1] * geo[(b * 3 + 1) * NN + n]
            + geo_wx[o * 3 + 2] * geo[(b * 3 + 2) * NN + n];
    float ssg = g / (1.f + fabsf(g));
    d_feat[(b * FD + 512 + o) * NN + n] = ssg * d_T[i];
}

// ---------------- launch ----------------
extern "C" void kernel_launch(void* const* d_in, const int* in_sizes, int n_in,
                              void* d_out, int out_size) {
    const float* x      = (const float*)d_in[0];
    const float* nodes  = (const float*)d_in[1];
    const float* nw     = (const float*)d_in[2];
    const float* geo    = (const float*)d_in[3];
    const int*   edges  = (const int*)d_in[4];
    const float* egw    = (const float*)d_in[5];
    const float* modes  = (const float*)d_in[6];
    const float* wc     = (const float*)d_in[7];
    const float* ws     = (const float*)d_in[8];
    const float* w0     = (const float*)d_in[9];
    const float* W      = (const float*)d_in[10];
    const float* gwM    = (const float*)d_in[11];
    const float* geo_wx = (const float*)d_in[12];
    const float* wx     = (const float*)d_in[13];
    const float* w2     = (const float*)d_in[14];
    float* outp = (float*)d_out;

    k_zero<<<(BB * NN + 255) / 256, 256>>>();
    k_bases<<<dim3(NN / 256, KK, BB), 256>>>(nodes, modes);
    k_copyx<<<BB * CC * NN / 256, 256>>>(x);
    k_xT<<<dim3(NN / 32, CC / 32, BB), dim3(32, 8)>>>(x);
    k_gemm1<<<dim3(128, BB), 256>>>(x, nw);
    k_wT<<<KK * CC * CC / 256, 256>>>(wc, ws);
    k_fmix<<<dim3(KK, BB), 64>>>();
    k_wcat_static<<<(BB * CC * 320 + 255) / 256, 256>>>(W, gwM, w2);
    k_bias<<<BB, 64>>>(w0);
    k_count<<<BB * EE / 256, 256>>>(edges);
    k_scan<<<BB, 1024>>>();
    k_fill<<<BB * EE / 256, 256>>>(edges);
    k_gather<<<BB * NN * 32 / 256, 256>>>(edges, egw);
    k_gT<<<dim3(NN / 32, 192 / 32, BB), dim3(32, 8)>>>();
    k_gemm_T<<<dim3(NN / 128, BB), 256>>>(wx, x);
    k_h<<<BB * CC * NN / 256, 256>>>(geo, geo_wx);
    k_gemm_final<<<dim3(NN / 128, BB), 256>>>(outp);
}

// round 4
// speedup vs baseline: 1.1112x; 1.1112x over previous
#include <cuda_runtime.h>
#include <math.h>

#define BB 2
#define CC 64
#define NN 16384
#define DD 3
#define KK 128
#define EE 262144
#define FD 576   // 128 cos + 128 sin + 64 x + 192 gradf + 64 h
#define NCH 32   // n-chunks for gemm1 partials

// ---------------- scratch (static device globals; no runtime alloc) ----------------
__device__ float d_feat[BB * FD * NN];        // feature matrix (B, 576, N)
__device__ float d_xT[BB * NN * CC];          // x transposed (B, N, C)
__device__ float d_gradf[BB * NN * 192];      // gather result (B, N, 192)
__device__ float d_xc[BB * CC * KK];
__device__ float d_xs[BB * CC * KK];
__device__ float d_x0[BB * CC];
__device__ float d_Wcat[BB * CC * FD];        // fused left matrix (B, 64, 576)
__device__ float d_bias[BB * CC];             // f_0
__device__ float d_T[BB * CC * NN];           // wx @ x
__device__ float d_wcT[KK * CC * CC];         // weights_c transposed to (k,i,o)
__device__ float d_wsT[KK * CC * CC];
__device__ float d_pc[BB * 2 * NCH * 64 * 64]; // gemm1 partials (cos)
__device__ float d_ps[BB * 2 * NCH * 64 * 64]; // gemm1 partials (sin)
__device__ int   d_cnt[BB * NN];
__device__ int   d_off[BB * (NN + 1)];
__device__ int   d_cur[BB * NN];
__device__ float4 d_epack[BB * EE];           // CSR payload: {src, w0, w1, w2}

// ---------------- fast sincos: Cody-Waite + poly, FMA pipe only ----------------
__device__ __forceinline__ void fast_sincos(float tv, float& sr, float& cr) {
    float fk = rintf(tv * 0.63661977236758134f);
    int q = (int)fk;
    float r = fmaf(fk, -1.5707963705062866f, tv);
    r = fmaf(fk, 4.3711388286737929e-8f, r);
    float r2 = r * r;
    float sp = -1.98412698e-4f;
    sp = fmaf(sp, r2, 8.3333310e-3f);
    sp = fmaf(sp, r2, -1.6666667e-1f);
    float sinr = fmaf(sp * r2, r, r);
    float cp = 2.48015873e-5f;
    cp = fmaf(cp, r2, -1.38888889e-3f);
    cp = fmaf(cp, r2, 4.16666667e-2f);
    cp = fmaf(cp, r2, -0.5f);
    float cosr = fmaf(cp, r2, 1.0f);
    float s_ = (q & 1) ? cosr : sinr;
    float c_ = (q & 1) ? sinr : cosr;
    if (q & 2) s_ = -s_;
    if ((q + 1) & 2) c_ = -c_;
    sr = s_; cr = c_;
}

// ---------------- zero counters ----------------
__global__ void k_zero() {
    int i = blockIdx.x * blockDim.x + threadIdx.x;
    if (i < BB * NN) d_cnt[i] = 0;
}

// ---------------- bases: one node per thread, loop over 128 modes ----------------
__global__ __launch_bounds__(256) void k_bases(const float* __restrict__ nodes,
                                               const float* __restrict__ modes) {
    __shared__ float sm[KK * 3];
    int t = threadIdx.x;
    for (int j = t; j < KK * 3; j += 256) sm[j] = modes[j];
    __syncthreads();
    int n = blockIdx.x * 256 + t;
    int b = blockIdx.y;
    float p0 = nodes[(b * NN + n) * 3 + 0];
    float p1 = nodes[(b * NN + n) * 3 + 1];
    float p2 = nodes[(b * NN + n) * 3 + 2];
    float* fc = &d_feat[(size_t)b * FD * NN + n];
    #pragma unroll 4
    for (int k = 0; k < KK; ++k) {
        float tv = fmaf(p0, sm[3 * k], fmaf(p1, sm[3 * k + 1], p2 * sm[3 * k + 2]));
        float s_, c_;
        fast_sincos(tv, s_, c_);
        fc[(size_t)k * NN] = c_;
        fc[(size_t)(KK + k) * NN] = s_;
    }
}

// ---------------- copy x -> feat rows [256,320) ----------------
__global__ void k_copyx(const float* __restrict__ x) {
    int i = blockIdx.x * 256 + threadIdx.x;
    int n = i & (NN - 1);
    int c = (i >> 14) & 63;
    int b = i >> 20;
    d_feat[(b * FD + 256 + c) * NN + n] = x[i];
}

// ---------------- transpose x -> xT (B,N,C) for edge gathers ----------------
__global__ void k_xT(const float* __restrict__ x) {
    __shared__ float tile[32][33];
    int b = blockIdx.z;
    int n0 = blockIdx.x * 32, c0 = blockIdx.y * 32;
    int tx = threadIdx.x, ty = threadIdx.y;   // (32, 8)
    for (int j = 0; j < 32; j += 8)
        tile[ty + j][tx] = x[(b * CC + c0 + ty + j) * NN + n0 + tx];
    __syncthreads();
    for (int j = 0; j < 32; j += 8)
        d_xT[(b * NN + n0 + ty + j) * CC + c0 + tx] = tile[tx][ty + j];
}

// ---------------- GEMM1: x_c/x_s partials, 4i x 4k x {c,s} register tile ----------
__global__ __launch_bounds__(256) void k_gemm1(const float* __restrict__ x,
                                               const float* __restrict__ nwp) {
    const int nc = blockIdx.x;         // n-chunk [0,NCH)
    const int kc = blockIdx.y;         // k-chunk [0,2)
    const int b  = blockIdx.z;
    const int NPC = NN / NCH;          // 512
    __shared__ float sxT[32][68];
    __shared__ float scT[32][68];
    __shared__ float ssT[32][68];
    int t = threadIdx.x;
    int ti = t & 15, tk = t >> 4;
    int i4 = ti * 4, k4 = tk * 4;
    float aC[4][4] = {}, aS[4][4] = {};
    for (int sub = 0; sub < NPC / 32; ++sub) {
        int n0 = nc * NPC + sub * 32;
        #pragma unroll
        for (int j = 0; j < 8; ++j) {
            int e = t + j * 256; int r = e >> 5, col = e & 31;
            sxT[col][r] = x[(b * CC + r) * NN + n0 + col] * nwp[b * NN + n0 + col];
            scT[col][r] = d_feat[(b * FD + kc * 64 + r) * NN + n0 + col];
            ssT[col][r] = d_feat[(b * FD + KK + kc * 64 + r) * NN + n0 + col];
        }
        __syncthreads();
        #pragma unroll 4
        for (int nn = 0; nn < 32; ++nn) {
            float4 xv = *reinterpret_cast<const float4*>(&sxT[nn][i4]);
            float4 cv = *reinterpret_cast<const float4*>(&scT[nn][k4]);
            float4 sv = *reinterpret_cast<const float4*>(&ssT[nn][k4]);
            const float* xp = &xv.x; const float* cp = &cv.x; const float* sp = &sv.x;
            #pragma unroll
            for (int a = 0; a < 4; ++a)
                #pragma unroll
                for (int bb = 0; bb < 4; ++bb) {
                    aC[a][bb] += xp[a] * cp[bb];
                    aS[a][bb] += xp[a] * sp[bb];
                }
        }
        __syncthreads();
    }
    int base = (((b * 2 + kc) * NCH) + nc) * 4096;
    #pragma unroll
    for (int a = 0; a < 4; ++a) {
        *reinterpret_cast<float4*>(&d_pc[base + (i4 + a) * 64 + k4]) =
            make_float4(aC[a][0], aC[a][1], aC[a][2], aC[a][3]);
        *reinterpret_cast<float4*>(&d_ps[base + (i4 + a) * 64 + k4]) =
            make_float4(aS[a][0], aS[a][1], aS[a][2], aS[a][3]);
    }
}

// ---------------- reduce gemm1 partials -> d_xc, d_xs ----------------
__global__ void k_red1() {
    int idx = blockIdx.x * 256 + threadIdx.x;   // BB*64*128
    int k = idx & 127; int i = (idx >> 7) & 63; int b = idx >> 13;
    int kc = k >> 6, kl = k & 63;
    int base = ((b * 2 + kc) * NCH) * 4096 + i * 64 + kl;
    float sC = 0.f, sS = 0.f;
    #pragma unroll 4
    for (int nc = 0; nc < NCH; ++nc) {
        sC += d_pc[base + nc * 4096];
        sS += d_ps[base + nc * 4096];
    }
    d_xc[(b * CC + i) * KK + k] = sC;
    d_xs[(b * CC + i) * KK + k] = -sS;
}

// ---------------- x0[b,i] = sum_n x*nw ----------------
__global__ void k_x0(const float* __restrict__ x, const float* __restrict__ nwp) {
    int b = blockIdx.x >> 6, i = blockIdx.x & 63;
    int t = threadIdx.x;
    float s = 0.f;
    for (int n = t; n < NN; n += 256)
        s += x[(b * CC + i) * NN + n] * nwp[b * NN + n];
    __shared__ float red[8];
    for (int o = 16; o > 0; o >>= 1) s += __shfl_down_sync(0xffffffffu, s, o);
    if ((t & 31) == 0) red[t >> 5] = s;
    __syncthreads();
    if (t == 0) {
        float tot = 0.f;
        for (int w = 0; w < 8; ++w) tot += red[w];
        d_x0[blockIdx.x] = tot;
    }
}

// ---------------- transpose weights_c/s (i,o,k) -> (k,i,o) ----------------
__global__ void k_wT(const float* __restrict__ wc, const float* __restrict__ ws) {
    int i = blockIdx.x * 256 + threadIdx.x;   // over KK*CC*CC
    int o = i & 63; int ii = (i >> 6) & 63; int k = i >> 12;
    d_wcT[i] = wc[(ii * 64 + o) * KK + k];
    d_wsT[i] = ws[(ii * 64 + o) * KK + k];
}

// ---------------- fourier mixing: f_c, f_s -> Wcat cols [0,256) ----------------
__global__ void k_fmix() {
    int k = blockIdx.x, b = blockIdx.y, o = threadIdx.x;
    __shared__ float sxc[64], sxs[64];
    sxc[o] = d_xc[(b * CC + o) * KK + k];
    sxs[o] = d_xs[(b * CC + o) * KK + k];
    __syncthreads();
    float fc = 0.f, fs = 0.f;
    for (int i = 0; i < 64; ++i) {
        float wc = d_wcT[(k * 64 + i) * 64 + o];
        float ws = d_wsT[(k * 64 + i) * 64 + o];
        fc += sxc[i] * wc - sxs[i] * ws;
        fs += sxs[i] * wc + sxc[i] * ws;
    }
    d_Wcat[(b * CC + o) * FD + k] = 2.f * fc;
    d_Wcat[(b * CC + o) * FD + KK + k] = -2.f * fs;
}

// ---------------- Wcat static columns: W, gw, w2 ----------------
__global__ void k_wcat_static(const float* __restrict__ W, const float* __restrict__ gwM,
                              const float* __restrict__ w2) {
    int i = blockIdx.x * 256 + threadIdx.x;   // over BB*CC*320
    if (i >= BB * CC * 320) return;
    int j = i % 320; int o = (i / 320) % CC; int b = i / (320 * CC);
    float v; int col;
    if (j < 64)       { v = W[o * 64 + j];           col = 256 + j; }
    else if (j < 256) { v = gwM[o * 192 + (j - 64)]; col = 320 + (j - 64); }
    else              { v = w2[o * 64 + (j - 256)];  col = 512 + (j - 256); }
    d_Wcat[(b * CC + o) * FD + col] = v;
}

// ---------------- bias f_0 = x_0 @ weights_0 ----------------
__global__ void k_bias(const float* __restrict__ w0) {
    int b = blockIdx.x, o = threadIdx.x;
    __shared__ float s0[64];
    s0[o] = d_x0[b * CC + o];
    __syncthreads();
    float f = 0.f;
    for (int i = 0; i < 64; ++i) f += s0[i] * w0[i * 64 + o];
    d_bias[b * CC + o] = f;
}

// ---------------- edge CSR: count -> scan -> fill(pack) ----------------
__global__ void k_count(const int* __restrict__ edges) {
    int i = blockIdx.x * 256 + threadIdx.x;   // b*EE + e
    int tgt = edges[2 * i];
    int b = i / EE;
    atomicAdd(&d_cnt[b * NN + tgt], 1);
}

__global__ void k_scan() {
    int b = blockIdx.x; int t = threadIdx.x;  // 1024 threads
    __shared__ int sm[1024];
    int vals[16]; int run = 0;
    #pragma unroll
    for (int j = 0; j < 16; ++j) {
        int v = d_cnt[b * NN + t * 16 + j];
        vals[j] = run; run += v;
    }
    sm[t] = run; __syncthreads();
    for (int off = 1; off < 1024; off <<= 1) {
        int v = (t >= off) ? sm[t - off] : 0;
        __syncthreads();
        sm[t] += v;
        __syncthreads();
    }
    int prev = (t > 0) ? sm[t - 1] : 0;
    #pragma unroll
    for (int j = 0; j < 16; ++j) {
        int val = prev + vals[j];
        d_off[b * (NN + 1) + t * 16 + j] = val;
        d_cur[b * NN + t * 16 + j] = val;
    }
    if (t == 1023) d_off[b * (NN + 1) + NN] = sm[1023];
}

__global__ void k_fill(const int* __restrict__ edges, const float* __restrict__ egw) {
    int i = blockIdx.x * 256 + threadIdx.x;   // b*EE + e
    int b = i / EE;
    int tgt = edges[2 * i];
    int src = edges[2 * i + 1];
    int slot = atomicAdd(&d_cur[b * NN + tgt], 1);
    float4 v;
    v.x = __int_as_float(src);
    v.y = egw[3 * i + 0];
    v.z = egw[3 * i + 1];
    v.w = egw[3 * i + 2];
    d_epack[b * EE + slot] = v;
}

// ---------------- gather: warp per node, register accumulation ----------------
__global__ void k_gather() {
    int wid = (blockIdx.x * blockDim.x + threadIdx.x) >> 5;
    int lane = threadIdx.x & 31;
    if (wid >= BB * NN) return;
    int b = wid >> 14, n = wid & (NN - 1);
    const float* xb = &d_xT[b * NN * CC];
    float t0 = xb[n * CC + lane], t1 = xb[n * CC + lane + 32];
    float a0 = 0, a1 = 0, a2 = 0, a3 = 0, a4 = 0, a5 = 0;
    int s = d_off[b * (NN + 1) + n], e_ = d_off[b * (NN + 1) + n + 1];
    for (int p = s; p < e_; ++p) {
        float4 v = d_epack[b * EE + p];
        int src = __float_as_int(v.x);
        float dd0 = xb[src * CC + lane] - t0;
        float dd1 = xb[src * CC + lane + 32] - t1;
        a0 += dd0 * v.y; a1 += dd0 * v.z; a2 += dd0 * v.w;
        a3 += dd1 * v.y; a4 += dd1 * v.z; a5 += dd1 * v.w;
    }
    float* g = &d_gradf[(b * NN + n) * 192];
    g[lane * 3 + 0] = a0; g[lane * 3 + 1] = a1; g[lane * 3 + 2] = a2;
    g[(lane + 32) * 3 + 0] = a3; g[(lane + 32) * 3 + 1] = a4; g[(lane + 32) * 3 + 2] = a5;
}

// ---------------- transpose gradf (N,192) -> feat rows [320,512) ----------------
__global__ void k_gT() {
    __shared__ float tile[32][33];
    int b = blockIdx.z;
    int n0 = blockIdx.x * 32, g0 = blockIdx.y * 32;
    int tx = threadIdx.x, ty = threadIdx.y;   // (32, 8)
    for (int j = 0; j < 32; j += 8)
        tile[ty + j][tx] = d_gradf[(b * NN + n0 + ty + j) * 192 + g0 + tx];
    __syncthreads();
    for (int j = 0; j < 32; j += 8)
        d_feat[(b * FD + 320 + g0 + ty + j) * NN + n0 + tx] = tile[tx][ty + j];
}

// ---------------- 64 x KD x N GEMM, 8x8 reg tile, pipelined loads ----------------
template <int KD, bool DOGELU>
__device__ __forceinline__ void gemm64_body(const float* __restrict__ A, int aStride,
                                            const float* __restrict__ Bm,
                                            const float* __restrict__ bias,
                                            float* __restrict__ outp) {
    __shared__ __align__(16) float As[16][68];
    __shared__ __align__(16) float Bs[16][256];
    const int b = blockIdx.y;
    const int n0 = blockIdx.x * 256;
    const int t = threadIdx.x;
    const int tm = t >> 5;       // row group: rows tm*8..tm*8+7
    const int tn = t & 31;       // col groups: 4*tn and 128+4*tn
    const int KT = KD / 16;
    float acc[8][8] = {};
    const float* Ab = A + b * aStride;
    const float* Bb = Bm + (size_t)b * KD * NN;
    const int ao = t >> 2, ak = (t & 3) * 4;

    float4 ra, rb[4];
    // preload kt = 0
    ra = *reinterpret_cast<const float4*>(&Ab[ao * KD + ak]);
    #pragma unroll
    for (int j = 0; j < 4; ++j) {
        int e = t + j * 256; int kk = e >> 6, nn = (e & 63) * 4;
        rb[j] = *reinterpret_cast<const float4*>(&Bb[(size_t)kk * NN + n0 + nn]);
    }
    for (int kt = 0; kt < KT; ++kt) {
        __syncthreads();
        As[ak][ao] = ra.x; As[ak + 1][ao] = ra.y; As[ak + 2][ao] = ra.z; As[ak + 3][ao] = ra.w;
        #pragma unroll
        for (int j = 0; j < 4; ++j) {
            int e = t + j * 256; int kk = e >> 6, nn = (e & 63) * 4;
            *reinterpret_cast<float4*>(&Bs[kk][nn]) = rb[j];
        }
        __syncthreads();
        if (kt + 1 < KT) {
            ra = *reinterpret_cast<const float4*>(&Ab[ao * KD + (kt + 1) * 16 + ak]);
            #pragma unroll
            for (int j = 0; j < 4; ++j) {
                int e = t + j * 256; int kk = e >> 6, nn = (e & 63) * 4;
                rb[j] = *reinterpret_cast<const float4*>(&Bb[(size_t)((kt + 1) * 16 + kk) * NN + n0 + nn]);
            }
        }
        #pragma unroll
        for (int kk = 0; kk < 16; ++kk) {
            float4 b0 = *reinterpret_cast<const float4*>(&Bs[kk][4 * tn]);
            float4 b1 = *reinterpret_cast<const float4*>(&Bs[kk][128 + 4 * tn]);
            float4 a01 = *reinterpret_cast<const float4*>(&As[kk][tm * 8]);
            float4 a23 = *reinterpret_cast<const float4*>(&As[kk][tm * 8 + 4]);
            const float* ap0 = &a01.x; const float* ap1 = &a23.x;
            #pragma unroll
            for (int r = 0; r < 8; ++r) {
                float av = (r < 4) ? ap0[r] : ap1[r - 4];
                acc[r][0] += av * b0.x; acc[r][1] += av * b0.y;
                acc[r][2] += av * b0.z; acc[r][3] += av * b0.w;
                acc[r][4] += av * b1.x; acc[r][5] += av * b1.y;
                acc[r][6] += av * b1.z; acc[r][7] += av * b1.w;
            }
        }
    }
    #pragma unroll
    for (int r = 0; r < 8; ++r) {
        int o = tm * 8 + r;
        float bs = DOGELU ? bias[b * CC + o] : 0.f;
        float4 v0, v1;
        float* p0 = &v0.x; float* p1 = &v1.x;
        #pragma unroll
        for (int j = 0; j < 4; ++j) {
            float u = acc[r][j] + bs;
            if (DOGELU) u = 0.5f * u * (1.f + erff(u * 0.70710678118654752f));
            p0[j] = u;
            float w = acc[r][4 + j] + bs;
            if (DOGELU) w = 0.5f * w * (1.f + erff(w * 0.70710678118654752f));
            p1[j] = w;
        }
        float* op = &outp[(size_t)(b * CC + o) * NN + n0];
        *reinterpret_cast<float4*>(&op[4 * tn]) = v0;
        *reinterpret_cast<float4*>(&op[128 + 4 * tn]) = v1;
    }
}

__global__ __launch_bounds__(256) void k_gemm_T(const float* __restrict__ wx,
                                                const float* __restrict__ x) {
    gemm64_body<64, false>(wx, 0, x, nullptr, d_T);
}

__global__ __launch_bounds__(256) void k_gemm_final(float* __restrict__ outp) {
    gemm64_body<576, true>(d_Wcat, CC * FD, d_feat, d_bias, outp);
}

// ---------------- h = softsign(geo_wx @ geo) * (wx @ x) -> feat rows [512,576) ------
__global__ void k_h(const float* __restrict__ geo, const float* __restrict__ geo_wx) {
    int i = blockIdx.x * 256 + threadIdx.x;   // BB*CC*NN
    int n = i & (NN - 1); int o = (i >> 14) & 63; int b = i >> 20;
    float g = geo_wx[o * 3 + 0] * geo[(b * 3 + 0) * NN + n]
            + geo_wx[o * 3 + 1] * geo[(b * 3 + 1) * NN + n]
            + geo_wx[o * 3 + 2] * geo[(b * 3 + 2) * NN + n];
    float ssg = g / (1.f + fabsf(g));
    d_feat[(b * FD + 512 + o) * NN + n] = ssg * d_T[i];
}

// ---------------- launch ----------------
extern "C" void kernel_launch(void* const* d_in, const int* in_sizes, int n_in,
                              void* d_out, int out_size) {
    const float* x      = (const float*)d_in[0];
    const float* nodes  = (const float*)d_in[1];
    const float* nw     = (const float*)d_in[2];
    const float* geo    = (const float*)d_in[3];
    const int*   edges  = (const int*)d_in[4];
    const float* egw    = (const float*)d_in[5];
    const float* modes  = (const float*)d_in[6];
    const float* wc     = (const float*)d_in[7];
    const float* ws     = (const float*)d_in[8];
    const float* w0     = (const float*)d_in[9];
    const float* W      = (const float*)d_in[10];
    const float* gwM    = (const float*)d_in[11];
    const float* geo_wx = (const float*)d_in[12];
    const float* wx     = (const float*)d_in[13];
    const float* w2     = (const float*)d_in[14];
    float* outp = (float*)d_out;

    k_zero<<<(BB * NN + 255) / 256, 256>>>();
    k_bases<<<dim3(NN / 256, BB), 256>>>(nodes, modes);
    k_copyx<<<BB * CC * NN / 256, 256>>>(x);
    k_xT<<<dim3(NN / 32, CC / 32, BB), dim3(32, 8)>>>(x);
    k_gemm1<<<dim3(NCH, 2, BB), 256>>>(x, nw);
    k_red1<<<BB * CC * KK / 256, 256>>>();
    k_x0<<<BB * CC, 256>>>(x, nw);
    k_wT<<<KK * CC * CC / 256, 256>>>(wc, ws);
    k_fmix<<<dim3(KK, BB), 64>>>();
    k_wcat_static<<<(BB * CC * 320 + 255) / 256, 256>>>(W, gwM, w2);
    k_bias<<<BB, 64>>>(w0);
    k_count<<<BB * EE / 256, 256>>>(edges);
    k_scan<<<BB, 1024>>>();
    k_fill<<<BB * EE / 256, 256>>>(edges, egw);
    k_gather<<<BB * NN * 32 / 256, 256>>>();
    k_gT<<<dim3(NN / 32, 192 / 32, BB), dim3(32, 8)>>>();
    k_gemm_T<<<dim3(NN / 256, BB), 256>>>(wx, x);
    k_h<<<BB * CC * NN / 256, 256>>>(geo, geo_wx);
    k_gemm_final<<<dim3(NN / 256, BB), 256>>>(outp);
}